// round 7
// baseline (speedup 1.0000x reference)
#include <cuda_runtime.h>
#include <cuda_fp16.h>
#include <math.h>

#define NN 50000
#define DD 128
#define EE 600000
#define ND ((size_t)NN * DD)
#define CAP 64                       // bucket capacity (Poisson(12), P(deg>=64)~1e-30)
#define NB ((NN + 255) / 256)

// Scratch (no cudaMalloc allowed): device globals.
__device__ float g_s[2][NN];         // gate projections, double-buffered by parity
__device__ float g_t[2][NN];
__device__ int g_cnt[NN];            // in-degree (counts up during build)
__device__ int g_bkt[NN * CAP];      // src node per slot, bucketed by dst
__device__ __half g_hf[2][NN * DD];  // fp16 feature mirror, double-buffered by parity
__device__ int g_is64;

__device__ __forceinline__ float warp_sum(float v) {
#pragma unroll
    for (int o = 16; o > 0; o >>= 1) v += __shfl_xor_sync(0xffffffffu, v, o);
    return v;
}

__device__ __forceinline__ float gate_alpha(float e0) {
    const float SC = 1.0507009873554804934193349852946f;
    const float AL = 1.6732632423543772848170429916717f;
    float u = e0 > 0.f ? SC * e0 : SC * AL * (__expf(e0) - 1.0f);
    return __fdividef(1.0f, 1.0f + __expf(-u));
}

// ---------------------------------------------------------------------------
// Launch 1: out[0] = l2norm(x) (fp32) + fp16 mirror (parity 0) + s/t parity-0
// projections. Housekeeping folded in: edge-dtype detect, g_cnt zeroing.
__global__ void norm_x_kernel(const float* __restrict__ x,
                              const float* __restrict__ w0,
                              float* __restrict__ out,
                              const int* __restrict__ ei32) {
    if (blockIdx.x == 0 && threadIdx.x == 0) {
        // int64 little-endian with values < 50000 => every odd int32 slot zero.
        int all0 = 1;
#pragma unroll
        for (int i = 1; i < 129; i += 2) all0 &= (ei32[i] == 0);
        g_is64 = all0;
    }
    int zi = blockIdx.x * 256 + threadIdx.x;
    if (blockIdx.x < NB && zi < NN) g_cnt[zi] = 0;

    int row = (blockIdx.x * blockDim.x + threadIdx.x) >> 5;
    int lane = threadIdx.x & 31;
    if (row >= NN) return;

    float4 v = ((const float4*)(x + (size_t)row * DD))[lane];
    float ss = v.x * v.x + v.y * v.y + v.z * v.z + v.w * v.w;
    ss = warp_sum(ss);
    float inv = 1.0f / fmaxf(sqrtf(ss), 1e-12f);

    float4 o = make_float4(v.x * inv, v.y * inv, v.z * inv, v.w * inv);
    ((float4*)(out + (size_t)row * DD))[lane] = o;

    __half2 q0 = __floats2half2_rn(o.x, o.y);
    __half2 q1 = __floats2half2_rn(o.z, o.w);
    uint2 u;
    u.x = *(unsigned*)&q0;
    u.y = *(unsigned*)&q1;
    ((uint2*)(g_hf[0] + (size_t)row * DD))[lane] = u;

    float4 a = ((const float4*)w0)[lane];
    float4 b = ((const float4*)(w0 + DD))[lane];
    float sd = o.x * a.x + o.y * a.y + o.z * a.z + o.w * a.w;
    float td = o.x * b.x + o.y * b.y + o.z * b.z + o.w * b.w;
    sd = warp_sum(sd);
    td = warp_sum(td);
    if (lane == 0) { g_s[0][row] = sd; g_t[0][row] = td; }
}

// Launch 2: single-pass bucket build (unpack + scatter, no scan needed).
__global__ void build_kernel(const void* __restrict__ ei) {
    int e = blockIdx.x * blockDim.x + threadIdx.x;
    if (e >= EE) return;
    int s, d;
    if (g_is64) {
        const long long* p = (const long long*)ei;
        s = (int)p[e];
        d = (int)p[EE + e];
    } else {
        const int* p = (const int*)ei;
        s = p[e];
        d = p[EE + e];
    }
    int pos = atomicAdd(&g_cnt[d], 1);
    if (pos < CAP) g_bkt[d * CAP + pos] = s;
}

// ---------------------------------------------------------------------------
// Launches 3-5: fused hop, warp per TWO dst rows (r0=2w, r1=2w+1).
// Interleaved gather loops double per-warp MLP. Inactive slots carry alpha=0
// and gather row 0 (L1-hot), avoiding inner-loop branches.
template <bool HAS_NEXT>
__global__ void hop_kernel(const float* __restrict__ bptr,
                           const float* __restrict__ noise_k,
                           const float* __restrict__ wk,
                           float* __restrict__ out,
                           int parity) {
    int pair = (blockIdx.x * blockDim.x + threadIdx.x) >> 5;
    int lane = threadIdx.x & 31;
    int r0 = pair * 2;
    if (r0 >= NN) return;
    int r1 = r0 + 1;   // NN is even, always valid

    const float* sbuf = g_s[parity];
    const __half* hf = g_hf[parity];
    float bb = *bptr;
    float tb0 = g_t[parity][r0] + bb;
    float tb1 = g_t[parity][r1] + bb;

    int deg0 = min(g_cnt[r0], CAP);
    int deg1 = min(g_cnt[r1], CAP);
    int mdeg = max(deg0, deg1);
    const int* bkt0 = g_bkt + r0 * CAP;
    const int* bkt1 = g_bkt + r1 * CAP;

    float4 acc0 = make_float4(0.f, 0.f, 0.f, 0.f);
    float4 acc1 = make_float4(0.f, 0.f, 0.f, 0.f);

    for (int base = 0; base < mdeg; base += 32) {
        int j = base + lane;
        int s0 = 0, s1 = 0;
        float a0 = 0.f, a1 = 0.f;
        if (j < deg0) {
            s0 = bkt0[j];
            a0 = gate_alpha(sbuf[s0] + tb0);
        }
        if (j < deg1) {
            s1 = bkt1[j];
            a1 = gate_alpha(sbuf[s1] + tb1);
        }
        int cm = min(32, mdeg - base);
        for (int k = 0; k < cm; k++) {
            int ss0 = __shfl_sync(0xffffffffu, s0, k);
            float aa0 = __shfl_sync(0xffffffffu, a0, k);
            int ss1 = __shfl_sync(0xffffffffu, s1, k);
            float aa1 = __shfl_sync(0xffffffffu, a1, k);
            uint2 u0 = ((const uint2*)(hf + (size_t)ss0 * DD))[lane];
            uint2 u1 = ((const uint2*)(hf + (size_t)ss1 * DD))[lane];
            float2 p0 = __half22float2(*(__half2*)&u0.x);
            float2 p1 = __half22float2(*(__half2*)&u0.y);
            float2 q0 = __half22float2(*(__half2*)&u1.x);
            float2 q1 = __half22float2(*(__half2*)&u1.y);
            acc0.x += aa0 * p0.x; acc0.y += aa0 * p0.y;
            acc0.z += aa0 * p1.x; acc0.w += aa0 * p1.y;
            acc1.x += aa1 * q0.x; acc1.y += aa1 * q0.y;
            acc1.z += aa1 * q1.x; acc1.w += aa1 * q1.y;
        }
    }

    float4 n0 = ((const float4*)(noise_k + (size_t)r0 * DD))[lane];
    float4 n1 = ((const float4*)(noise_k + (size_t)r1 * DD))[lane];
    acc0.x += 0.1f * n0.x; acc0.y += 0.1f * n0.y;
    acc0.z += 0.1f * n0.z; acc0.w += 0.1f * n0.w;
    acc1.x += 0.1f * n1.x; acc1.y += 0.1f * n1.y;
    acc1.z += 0.1f * n1.z; acc1.w += 0.1f * n1.w;

    float ss0 = warp_sum(acc0.x * acc0.x + acc0.y * acc0.y +
                         acc0.z * acc0.z + acc0.w * acc0.w);
    float ss1 = warp_sum(acc1.x * acc1.x + acc1.y * acc1.y +
                         acc1.z * acc1.z + acc1.w * acc1.w);
    float inv0 = 1.0f / fmaxf(sqrtf(ss0), 1e-12f);
    float inv1 = 1.0f / fmaxf(sqrtf(ss1), 1e-12f);

    float4 o0 = make_float4(acc0.x * inv0, acc0.y * inv0, acc0.z * inv0, acc0.w * inv0);
    float4 o1 = make_float4(acc1.x * inv1, acc1.y * inv1, acc1.z * inv1, acc1.w * inv1);
    ((float4*)(out + (size_t)r0 * DD))[lane] = o0;
    ((float4*)(out + (size_t)r1 * DD))[lane] = o1;

    if (HAS_NEXT) {
        int np = parity ^ 1;
        __half2 h00 = __floats2half2_rn(o0.x, o0.y);
        __half2 h01 = __floats2half2_rn(o0.z, o0.w);
        __half2 h10 = __floats2half2_rn(o1.x, o1.y);
        __half2 h11 = __floats2half2_rn(o1.z, o1.w);
        uint2 u0, u1;
        u0.x = *(unsigned*)&h00; u0.y = *(unsigned*)&h01;
        u1.x = *(unsigned*)&h10; u1.y = *(unsigned*)&h11;
        ((uint2*)(g_hf[np] + (size_t)r0 * DD))[lane] = u0;
        ((uint2*)(g_hf[np] + (size_t)r1 * DD))[lane] = u1;

        float4 a = ((const float4*)wk)[lane];
        float4 b = ((const float4*)(wk + DD))[lane];
        float sd0 = warp_sum(o0.x * a.x + o0.y * a.y + o0.z * a.z + o0.w * a.w);
        float td0 = warp_sum(o0.x * b.x + o0.y * b.y + o0.z * b.z + o0.w * b.w);
        float sd1 = warp_sum(o1.x * a.x + o1.y * a.y + o1.z * a.z + o1.w * a.w);
        float td1 = warp_sum(o1.x * b.x + o1.y * b.y + o1.z * b.z + o1.w * b.w);
        if (lane == 0) {
            g_s[np][r0] = sd0; g_t[np][r0] = td0;
            g_s[np][r1] = sd1; g_t[np][r1] = td1;
        }
    }
}

// ---------------------------------------------------------------------------
extern "C" void kernel_launch(void* const* d_in, const int* in_sizes, int n_in,
                              void* d_out, int out_size) {
    const float* x = (const float*)d_in[0];
    const void* ei = d_in[1];
    const float* attn_w = (const float*)d_in[2];
    const float* attn_b = (const float*)d_in[3];
    const float* noise = (const float*)d_in[4];
    float* out = (float*)d_out;

    const int NORM_GRID = (NN + 7) / 8;        // warp per row
    const int HOP_GRID = (NN / 2 + 7) / 8;     // warp per row-pair
    const int E256 = (EE + 255) / 256;

    // 1: norm(x) + fp16 mirror(0) + detect + cnt-zero
    norm_x_kernel<<<NORM_GRID, 256>>>(x, attn_w, out, (const int*)ei);
    // 2: bucket CSR build (single pass, no scan)
    build_kernel<<<E256, 256>>>(ei);
    // 3-5: hops (parity chain 0 -> 1 -> 0)
    hop_kernel<true><<<HOP_GRID, 256>>>(attn_b + 0, noise,
                                        attn_w + 2 * DD, out + ND, 0);
    hop_kernel<true><<<HOP_GRID, 256>>>(attn_b + 1, noise + ND,
                                        attn_w + 4 * DD, out + 2 * ND, 1);
    hop_kernel<false><<<HOP_GRID, 256>>>(attn_b + 2, noise + 2 * ND,
                                         attn_w, out + 3 * ND, 0);
}

// round 8
// speedup vs baseline: 1.0520x; 1.0520x over previous
#include <cuda_runtime.h>
#include <cuda_fp16.h>
#include <math.h>

#define NN 50000
#define DD 128
#define EE 600000
#define ND ((size_t)NN * DD)
#define CAP 64                       // bucket capacity (Poisson(12), P(deg>=64)~1e-30)
#define NB ((NN + 255) / 256)

// Scratch (no cudaMalloc allowed): device globals.
__device__ float g_s[2][NN];         // gate projections, double-buffered by parity
__device__ float g_t[2][NN];
__device__ int g_cnt[NN];            // in-degree (counts up during build)
__device__ int g_bkt[NN * CAP];      // src node per slot, bucketed by dst
__device__ __half g_hf[2][NN * DD];  // fp16 feature mirror, double-buffered by parity
__device__ int g_is64;

__device__ __forceinline__ float warp_sum(float v) {
#pragma unroll
    for (int o = 16; o > 0; o >>= 1) v += __shfl_xor_sync(0xffffffffu, v, o);
    return v;
}

// Fast gate: sigmoid(selu(e)). __expf = MUFU ex2 sequence; error ~1e-7,
// invisible next to the 1.9e-4 fp16-mirror floor.
__device__ __forceinline__ float gate_alpha(float e0) {
    const float SC = 1.0507009873554804934193349852946f;
    const float AL = 1.6732632423543772848170429916717f;
    float u = e0 > 0.f ? SC * e0 : SC * AL * (__expf(e0) - 1.0f);
    return __fdividef(1.0f, 1.0f + __expf(-u));
}

// ---------------------------------------------------------------------------
// Launch 1: out[0] = l2norm(x) (fp32) + fp16 mirror (parity 0) + s/t parity-0
// projections. Housekeeping folded in: edge-dtype detect, g_cnt zeroing.
__global__ void norm_x_kernel(const float* __restrict__ x,
                              const float* __restrict__ w0,
                              float* __restrict__ out,
                              const int* __restrict__ ei32) {
    if (blockIdx.x == 0 && threadIdx.x == 0) {
        // int64 little-endian with values < 50000 => every odd int32 slot zero.
        int all0 = 1;
#pragma unroll
        for (int i = 1; i < 129; i += 2) all0 &= (ei32[i] == 0);
        g_is64 = all0;
    }
    int zi = blockIdx.x * 256 + threadIdx.x;
    if (blockIdx.x < NB && zi < NN) g_cnt[zi] = 0;

    int row = (blockIdx.x * blockDim.x + threadIdx.x) >> 5;
    int lane = threadIdx.x & 31;
    if (row >= NN) return;

    float4 v = ((const float4*)(x + (size_t)row * DD))[lane];
    float ss = v.x * v.x + v.y * v.y + v.z * v.z + v.w * v.w;
    ss = warp_sum(ss);
    float inv = 1.0f / fmaxf(sqrtf(ss), 1e-12f);

    float4 o = make_float4(v.x * inv, v.y * inv, v.z * inv, v.w * inv);
    ((float4*)(out + (size_t)row * DD))[lane] = o;

    __half2 q0 = __floats2half2_rn(o.x, o.y);
    __half2 q1 = __floats2half2_rn(o.z, o.w);
    uint2 u;
    u.x = *(unsigned*)&q0;
    u.y = *(unsigned*)&q1;
    ((uint2*)(g_hf[0] + (size_t)row * DD))[lane] = u;

    float4 a = ((const float4*)w0)[lane];
    float4 b = ((const float4*)(w0 + DD))[lane];
    float sd = o.x * a.x + o.y * a.y + o.z * a.z + o.w * a.w;
    float td = o.x * b.x + o.y * b.y + o.z * b.z + o.w * b.w;
    sd = warp_sum(sd);
    td = warp_sum(td);
    if (lane == 0) { g_s[0][row] = sd; g_t[0][row] = td; }
}

// Launch 2: single-pass bucket build (unpack + scatter, no scan needed).
__global__ void build_kernel(const void* __restrict__ ei) {
    int e = blockIdx.x * blockDim.x + threadIdx.x;
    if (e >= EE) return;
    int s, d;
    if (g_is64) {
        const long long* p = (const long long*)ei;
        s = (int)p[e];
        d = (int)p[EE + e];
    } else {
        const int* p = (const int*)ei;
        s = p[e];
        d = p[EE + e];
    }
    int pos = atomicAdd(&g_cnt[d], 1);
    if (pos < CAP) g_bkt[d * CAP + pos] = s;
}

// ---------------------------------------------------------------------------
// Launches 3-5: fused hop, warp per dst row (R6 structure: occ ~80%).
// Gate phase: lanes 0..deg-1 compute alphas in parallel (fast-math MUFU).
// Gather phase: broadcast loop UNROLLED x2 with dual accumulators — two
// independent 256B row gathers in flight per iteration, half the FADD chain.
template <bool HAS_NEXT>
__global__ void hop_kernel(const float* __restrict__ bptr,
                           const float* __restrict__ noise_k,
                           const float* __restrict__ wk,
                           float* __restrict__ out,
                           int parity) {
    int row = (blockIdx.x * blockDim.x + threadIdx.x) >> 5;
    int lane = threadIdx.x & 31;
    if (row >= NN) return;

    const float* sbuf = g_s[parity];
    const __half* hf = g_hf[parity];
    float tb = g_t[parity][row] + *bptr;

    int deg = min(g_cnt[row], CAP);
    const int* bkt = g_bkt + row * CAP;

    float4 accA = make_float4(0.f, 0.f, 0.f, 0.f);
    float4 accB = make_float4(0.f, 0.f, 0.f, 0.f);

    for (int base = 0; base < deg; base += 32) {
        int j = base + lane;
        int sj = 0;
        float al = 0.f;
        if (j < deg) {
            sj = bkt[j];
            al = gate_alpha(sbuf[sj] + tb);
        }
        int cnt = min(32, deg - base);
        int k = 0;
        for (; k + 1 < cnt; k += 2) {
            int s0 = __shfl_sync(0xffffffffu, sj, k);
            float a0 = __shfl_sync(0xffffffffu, al, k);
            int s1 = __shfl_sync(0xffffffffu, sj, k + 1);
            float a1 = __shfl_sync(0xffffffffu, al, k + 1);
            uint2 u0 = ((const uint2*)(hf + (size_t)s0 * DD))[lane];
            uint2 u1 = ((const uint2*)(hf + (size_t)s1 * DD))[lane];
            float2 p0 = __half22float2(*(__half2*)&u0.x);
            float2 p1 = __half22float2(*(__half2*)&u0.y);
            float2 q0 = __half22float2(*(__half2*)&u1.x);
            float2 q1 = __half22float2(*(__half2*)&u1.y);
            accA.x += a0 * p0.x; accA.y += a0 * p0.y;
            accA.z += a0 * p1.x; accA.w += a0 * p1.y;
            accB.x += a1 * q0.x; accB.y += a1 * q0.y;
            accB.z += a1 * q1.x; accB.w += a1 * q1.y;
        }
        if (k < cnt) {
            int s0 = __shfl_sync(0xffffffffu, sj, k);
            float a0 = __shfl_sync(0xffffffffu, al, k);
            uint2 u0 = ((const uint2*)(hf + (size_t)s0 * DD))[lane];
            float2 p0 = __half22float2(*(__half2*)&u0.x);
            float2 p1 = __half22float2(*(__half2*)&u0.y);
            accA.x += a0 * p0.x; accA.y += a0 * p0.y;
            accA.z += a0 * p1.x; accA.w += a0 * p1.y;
        }
    }

    float4 acc = make_float4(accA.x + accB.x, accA.y + accB.y,
                             accA.z + accB.z, accA.w + accB.w);

    float4 n = ((const float4*)(noise_k + (size_t)row * DD))[lane];
    acc.x += 0.1f * n.x; acc.y += 0.1f * n.y;
    acc.z += 0.1f * n.z; acc.w += 0.1f * n.w;

    float ss = acc.x * acc.x + acc.y * acc.y + acc.z * acc.z + acc.w * acc.w;
    ss = warp_sum(ss);
    float inv = 1.0f / fmaxf(sqrtf(ss), 1e-12f);

    float4 o = make_float4(acc.x * inv, acc.y * inv, acc.z * inv, acc.w * inv);
    ((float4*)(out + (size_t)row * DD))[lane] = o;

    if (HAS_NEXT) {
        int np = parity ^ 1;
        __half2 q0 = __floats2half2_rn(o.x, o.y);
        __half2 q1 = __floats2half2_rn(o.z, o.w);
        uint2 u;
        u.x = *(unsigned*)&q0;
        u.y = *(unsigned*)&q1;
        ((uint2*)(g_hf[np] + (size_t)row * DD))[lane] = u;

        float4 a = ((const float4*)wk)[lane];
        float4 b = ((const float4*)(wk + DD))[lane];
        float sd = warp_sum(o.x * a.x + o.y * a.y + o.z * a.z + o.w * a.w);
        float td = warp_sum(o.x * b.x + o.y * b.y + o.z * b.z + o.w * b.w);
        if (lane == 0) { g_s[np][row] = sd; g_t[np][row] = td; }
    }
}

// ---------------------------------------------------------------------------
extern "C" void kernel_launch(void* const* d_in, const int* in_sizes, int n_in,
                              void* d_out, int out_size) {
    const float* x = (const float*)d_in[0];
    const void* ei = d_in[1];
    const float* attn_w = (const float*)d_in[2];
    const float* attn_b = (const float*)d_in[3];
    const float* noise = (const float*)d_in[4];
    float* out = (float*)d_out;

    const int NORM_GRID = (NN + 7) / 8;   // warp per row, 256-thread blocks
    const int E256 = (EE + 255) / 256;

    // 1: norm(x) + fp16 mirror(0) + detect + cnt-zero
    norm_x_kernel<<<NORM_GRID, 256>>>(x, attn_w, out, (const int*)ei);
    // 2: bucket CSR build (single pass, no scan)
    build_kernel<<<E256, 256>>>(ei);
    // 3-5: hops (parity chain 0 -> 1 -> 0)
    hop_kernel<true><<<NORM_GRID, 256>>>(attn_b + 0, noise,
                                         attn_w + 2 * DD, out + ND, 0);
    hop_kernel<true><<<NORM_GRID, 256>>>(attn_b + 1, noise + ND,
                                         attn_w + 4 * DD, out + 2 * ND, 1);
    hop_kernel<false><<<NORM_GRID, 256>>>(attn_b + 2, noise + 2 * ND,
                                          attn_w, out + 3 * ND, 0);
}

// round 9
// speedup vs baseline: 1.2150x; 1.1549x over previous
#include <cuda_runtime.h>
#include <cuda_fp16.h>
#include <math.h>

#define NN 50000
#define DD 128
#define EE 600000
#define ND ((size_t)NN * DD)
#define CAP 64                       // bucket capacity (Poisson(12), P(deg>=64)~1e-30)
#define NB ((NN + 255) / 256)

// Scratch (no cudaMalloc allowed): device globals.
__device__ float g_s[2][NN];         // gate projections, double-buffered by parity
__device__ float g_t[2][NN];
__device__ int g_cnt[NN];            // in-degree (counts up during build)
__device__ int g_bkt[NN * CAP];      // src node per slot, bucketed by dst
__device__ __half g_hf[2][NN * DD];  // fp16 feature mirror, double-buffered by parity
__device__ int g_is64;

__device__ __forceinline__ float warp_sum(float v) {
#pragma unroll
    for (int o = 16; o > 0; o >>= 1) v += __shfl_xor_sync(0xffffffffu, v, o);
    return v;
}

// Fast gate: sigmoid(selu(e)).
__device__ __forceinline__ float gate_alpha(float e0) {
    const float SC = 1.0507009873554804934193349852946f;
    const float AL = 1.6732632423543772848170429916717f;
    float u = e0 > 0.f ? SC * e0 : SC * AL * (__expf(e0) - 1.0f);
    return __fdividef(1.0f, 1.0f + __expf(-u));
}

// ---------------------------------------------------------------------------
// Launch 1: out[0] = l2norm(x) (fp32) + fp16 mirror (parity 0) + s/t parity-0
// projections. Housekeeping folded in: edge-dtype detect, g_cnt zeroing.
__global__ void norm_x_kernel(const float* __restrict__ x,
                              const float* __restrict__ w0,
                              float* __restrict__ out,
                              const int* __restrict__ ei32) {
    if (blockIdx.x == 0 && threadIdx.x == 0) {
        int all0 = 1;
#pragma unroll
        for (int i = 1; i < 129; i += 2) all0 &= (ei32[i] == 0);
        g_is64 = all0;
    }
    int zi = blockIdx.x * 256 + threadIdx.x;
    if (blockIdx.x < NB && zi < NN) g_cnt[zi] = 0;

    int row = (blockIdx.x * blockDim.x + threadIdx.x) >> 5;
    int lane = threadIdx.x & 31;
    if (row >= NN) return;

    float4 v = ((const float4*)(x + (size_t)row * DD))[lane];
    float ss = v.x * v.x + v.y * v.y + v.z * v.z + v.w * v.w;
    ss = warp_sum(ss);
    float inv = 1.0f / fmaxf(sqrtf(ss), 1e-12f);

    float4 o = make_float4(v.x * inv, v.y * inv, v.z * inv, v.w * inv);
    ((float4*)(out + (size_t)row * DD))[lane] = o;

    __half2 q0 = __floats2half2_rn(o.x, o.y);
    __half2 q1 = __floats2half2_rn(o.z, o.w);
    uint2 u;
    u.x = *(unsigned*)&q0;
    u.y = *(unsigned*)&q1;
    ((uint2*)(g_hf[0] + (size_t)row * DD))[lane] = u;

    float4 a = ((const float4*)w0)[lane];
    float4 b = ((const float4*)(w0 + DD))[lane];
    float sd = warp_sum(o.x * a.x + o.y * a.y + o.z * a.z + o.w * a.w);
    float td = warp_sum(o.x * b.x + o.y * b.y + o.z * b.z + o.w * b.w);
    if (lane == 0) { g_s[0][row] = sd; g_t[0][row] = td; }
}

// Launch 2: single-pass bucket build (unpack + scatter, no scan needed).
__global__ void build_kernel(const void* __restrict__ ei) {
    int e = blockIdx.x * blockDim.x + threadIdx.x;
    if (e >= EE) return;
    int s, d;
    if (g_is64) {
        const long long* p = (const long long*)ei;
        s = (int)p[e];
        d = (int)p[EE + e];
    } else {
        const int* p = (const int*)ei;
        s = p[e];
        d = p[EE + e];
    }
    int pos = atomicAdd(&g_cnt[d], 1);
    if (pos < CAP) g_bkt[d * CAP + pos] = s;
}

// ---------------------------------------------------------------------------
// Launches 3-5: fused hop, warp per dst row.
// Gate phase: lanes 0..deg-1 compute alphas in parallel; padding lanes carry
// alpha=0, src=0 so the gather loop runs branch-free on groups of 4.
// Gather phase: batch-4 pipeline — 4 independent 256B gathers issued into
// separate registers before any consumption (explicit MLP=4 per warp).
template <bool HAS_NEXT>
__global__ void hop_kernel(const float* __restrict__ bptr,
                           const float* __restrict__ noise_k,
                           const float* __restrict__ wk,
                           float* __restrict__ out,
                           int parity) {
    int row = (blockIdx.x * blockDim.x + threadIdx.x) >> 5;
    int lane = threadIdx.x & 31;
    if (row >= NN) return;

    const float* sbuf = g_s[parity];
    const __half* hf = g_hf[parity];
    float tb = g_t[parity][row] + *bptr;

    int deg = min(g_cnt[row], CAP);
    const int* bkt = g_bkt + row * CAP;

    float4 acc = make_float4(0.f, 0.f, 0.f, 0.f);

    for (int base = 0; base < deg; base += 32) {
        int j = base + lane;
        int sj = 0;
        float al = 0.f;
        if (j < deg) {
            sj = bkt[j];
            al = gate_alpha(sbuf[sj] + tb);
        }
        int cnt = min(32, deg - base);
        int cnt4 = (cnt + 3) & ~3;          // round up; padding lanes have al=0
        for (int k = 0; k < cnt4; k += 4) {
            int s0 = __shfl_sync(0xffffffffu, sj, k);
            int s1 = __shfl_sync(0xffffffffu, sj, k + 1);
            int s2 = __shfl_sync(0xffffffffu, sj, k + 2);
            int s3 = __shfl_sync(0xffffffffu, sj, k + 3);
            float a0 = __shfl_sync(0xffffffffu, al, k);
            float a1 = __shfl_sync(0xffffffffu, al, k + 1);
            float a2 = __shfl_sync(0xffffffffu, al, k + 2);
            float a3 = __shfl_sync(0xffffffffu, al, k + 3);
            uint2 u0 = ((const uint2*)(hf + (size_t)s0 * DD))[lane];
            uint2 u1 = ((const uint2*)(hf + (size_t)s1 * DD))[lane];
            uint2 u2 = ((const uint2*)(hf + (size_t)s2 * DD))[lane];
            uint2 u3 = ((const uint2*)(hf + (size_t)s3 * DD))[lane];
            float2 p0 = __half22float2(*(__half2*)&u0.x);
            float2 p1 = __half22float2(*(__half2*)&u0.y);
            acc.x += a0 * p0.x; acc.y += a0 * p0.y;
            acc.z += a0 * p1.x; acc.w += a0 * p1.y;
            p0 = __half22float2(*(__half2*)&u1.x);
            p1 = __half22float2(*(__half2*)&u1.y);
            acc.x += a1 * p0.x; acc.y += a1 * p0.y;
            acc.z += a1 * p1.x; acc.w += a1 * p1.y;
            p0 = __half22float2(*(__half2*)&u2.x);
            p1 = __half22float2(*(__half2*)&u2.y);
            acc.x += a2 * p0.x; acc.y += a2 * p0.y;
            acc.z += a2 * p1.x; acc.w += a2 * p1.y;
            p0 = __half22float2(*(__half2*)&u3.x);
            p1 = __half22float2(*(__half2*)&u3.y);
            acc.x += a3 * p0.x; acc.y += a3 * p0.y;
            acc.z += a3 * p1.x; acc.w += a3 * p1.y;
        }
    }

    float4 n = ((const float4*)(noise_k + (size_t)row * DD))[lane];
    acc.x += 0.1f * n.x; acc.y += 0.1f * n.y;
    acc.z += 0.1f * n.z; acc.w += 0.1f * n.w;

    float ss = acc.x * acc.x + acc.y * acc.y + acc.z * acc.z + acc.w * acc.w;
    ss = warp_sum(ss);
    float inv = 1.0f / fmaxf(sqrtf(ss), 1e-12f);

    float4 o = make_float4(acc.x * inv, acc.y * inv, acc.z * inv, acc.w * inv);
    ((float4*)(out + (size_t)row * DD))[lane] = o;

    if (HAS_NEXT) {
        int np = parity ^ 1;
        __half2 q0 = __floats2half2_rn(o.x, o.y);
        __half2 q1 = __floats2half2_rn(o.z, o.w);
        uint2 u;
        u.x = *(unsigned*)&q0;
        u.y = *(unsigned*)&q1;
        ((uint2*)(g_hf[np] + (size_t)row * DD))[lane] = u;

        float4 a = ((const float4*)wk)[lane];
        float4 b = ((const float4*)(wk + DD))[lane];
        float sd = warp_sum(o.x * a.x + o.y * a.y + o.z * a.z + o.w * a.w);
        float td = warp_sum(o.x * b.x + o.y * b.y + o.z * b.z + o.w * b.w);
        if (lane == 0) { g_s[np][row] = sd; g_t[np][row] = td; }
    }
}

// ---------------------------------------------------------------------------
extern "C" void kernel_launch(void* const* d_in, const int* in_sizes, int n_in,
                              void* d_out, int out_size) {
    const float* x = (const float*)d_in[0];
    const void* ei = d_in[1];
    const float* attn_w = (const float*)d_in[2];
    const float* attn_b = (const float*)d_in[3];
    const float* noise = (const float*)d_in[4];
    float* out = (float*)d_out;

    const int NORM_GRID = (NN + 7) / 8;   // warp per row, 256-thread blocks
    const int E256 = (EE + 255) / 256;

    norm_x_kernel<<<NORM_GRID, 256>>>(x, attn_w, out, (const int*)ei);
    build_kernel<<<E256, 256>>>(ei);
    hop_kernel<true><<<NORM_GRID, 256>>>(attn_b + 0, noise,
                                         attn_w + 2 * DD, out + ND, 0);
    hop_kernel<true><<<NORM_GRID, 256>>>(attn_b + 1, noise + ND,
                                         attn_w + 4 * DD, out + 2 * ND, 1);
    hop_kernel<false><<<NORM_GRID, 256>>>(attn_b + 2, noise + 2 * ND,
                                          attn_w, out + 3 * ND, 0);
}